// round 2
// baseline (speedup 1.0000x reference)
#include <cuda_runtime.h>
#include <cstdint>
#include <cstddef>

#define NMAX 100352
#define DIM 128

// ---------------- scratch (static device globals; no allocations) ----------
__device__ float g_xf[(size_t)NMAX * DIM];     // projected features   [N,128]
__device__ float g_msg[(size_t)NMAX * DIM];    // segment sums         [N,128]
__device__ float g_cnt[NMAX];                  // in-degree (float)
__device__ float g_Bc[256 * 256];              // combined/interleaved weights
__device__ int   g_idx64;                      // 1 if index tensors are int64

// ---------------- dtype-robust index load ----------------------------------
__device__ __forceinline__ long long load_idx(const void* p, int i) {
    if (g_idx64) return reinterpret_cast<const long long*>(p)[i];
    return (long long)reinterpret_cast<const int*>(p)[i];
}

// Detect whether edge_index is int64 or int32. int64 data read as int64 gives
// values in [0,n); int32 data read as int64 gives (v0 | v1<<32), essentially
// never in range for random indices. Deterministic per input.
__global__ void k_detect(const void* ei, int n) {
    if (blockIdx.x == 0 && threadIdx.x == 0) {
        const long long* p = reinterpret_cast<const long long*>(ei);
        int ok = 1;
        for (int i = 0; i < 16; i++) {
            long long v = p[i];
            if (v < 0 || v >= (long long)n) ok = 0;
        }
        g_idx64 = ok;
    }
}

// ---------------- K0: zero scratch ------------------------------------------
__global__ void k_zero(int n) {
    const float4 z = make_float4(0.f, 0.f, 0.f, 0.f);
    int total4 = n * (DIM / 4);
    for (int i = blockIdx.x * blockDim.x + threadIdx.x; i < total4;
         i += gridDim.x * blockDim.x)
        reinterpret_cast<float4*>(g_msg)[i] = z;
    for (int i = blockIdx.x * blockDim.x + threadIdx.x; i < n;
         i += gridDim.x * blockDim.x)
        g_cnt[i] = 0.f;
}

// ---------------- K1: xf = [x | pos/50 | len/500] @ fp_w + fp_b -------------
// 128x128 tile, K=130 (padded to 136), 256 threads, 8x8 microtile.
__global__ __launch_bounds__(256) void k_featproj(
    const float* __restrict__ x, const void* __restrict__ pos,
    const void* __restrict__ len, const float* __restrict__ fpw,
    const float* __restrict__ fpb, int n)
{
    __shared__ float As[8][132];   // padded: conflict-free transpose stores
    __shared__ float Bs[8][128];

    const int tid  = threadIdx.x;
    const int row0 = blockIdx.x * 128;
    const int ty   = tid >> 4;     // 16 row groups
    const int tx   = tid & 15;     // 16 col groups

    float acc[8][8];
#pragma unroll
    for (int i = 0; i < 8; i++)
#pragma unroll
        for (int j = 0; j < 8; j++) acc[i][j] = 0.f;

    const int rl  = tid >> 1;            // 128 rows
    const int kq  = (tid & 1) * 4;       // 0 or 4
    const int bkr = tid >> 5;            // 8 B rows
    const int bj  = (tid & 31) * 4;      // 128 B cols

    for (int k0 = 0; k0 < 136; k0 += 8) {
        // ---- load A fragment
        float4 va = make_float4(0.f, 0.f, 0.f, 0.f);
        const int r  = row0 + rl;
        const int ka = k0 + kq;
        if (r < n) {
            if (ka + 3 < 128) {
                va = *reinterpret_cast<const float4*>(x + (size_t)r * 128 + ka);
            } else if (ka == 128) {   // tail: pos, len, 0, 0
                va.x = (float)load_idx(pos, r) * (1.0f / 50.0f);
                va.y = (float)load_idx(len, r) * (1.0f / 500.0f);
            }
        }
        // ---- load B fragment
        float4 vb = make_float4(0.f, 0.f, 0.f, 0.f);
        const int kb = k0 + bkr;
        if (kb < 130)
            vb = *reinterpret_cast<const float4*>(fpw + (size_t)kb * 128 + bj);

        __syncthreads();
        As[kq + 0][rl] = va.x;
        As[kq + 1][rl] = va.y;
        As[kq + 2][rl] = va.z;
        As[kq + 3][rl] = va.w;
        *reinterpret_cast<float4*>(&Bs[bkr][bj]) = vb;
        __syncthreads();

#pragma unroll
        for (int kk = 0; kk < 8; kk++) {
            float a[8], b[8];
            *reinterpret_cast<float4*>(a)     = *reinterpret_cast<const float4*>(&As[kk][ty * 8]);
            *reinterpret_cast<float4*>(a + 4) = *reinterpret_cast<const float4*>(&As[kk][ty * 8 + 4]);
            *reinterpret_cast<float4*>(b)     = *reinterpret_cast<const float4*>(&Bs[kk][tx * 8]);
            *reinterpret_cast<float4*>(b + 4) = *reinterpret_cast<const float4*>(&Bs[kk][tx * 8 + 4]);
#pragma unroll
            for (int i = 0; i < 8; i++)
#pragma unroll
                for (int j = 0; j < 8; j++)
                    acc[i][j] += a[i] * b[j];
        }
    }

#pragma unroll
    for (int i = 0; i < 8; i++) {
        const int r = row0 + ty * 8 + i;
        if (r < n) {
#pragma unroll
            for (int j4 = 0; j4 < 8; j4 += 4) {
                const int c = tx * 8 + j4;
                float4 o;
                o.x = acc[i][j4 + 0] + fpb[c + 0];
                o.y = acc[i][j4 + 1] + fpb[c + 1];
                o.z = acc[i][j4 + 2] + fpb[c + 2];
                o.w = acc[i][j4 + 3] + fpb[c + 3];
                *reinterpret_cast<float4*>(g_xf + (size_t)r * 128 + c) = o;
            }
        }
    }
}

// ---------------- K_bc: build combined, column-interleaved B (256x256) ------
// col 2j   : k<128 -> lin_l_w[k][j]      ; k>=128 -> lin_r_w[k-128][j]
// col 2j+1 : k<128 -> 0                  ; k>=128 -> res_w[k-128][j]
__global__ void k_bc(const float* __restrict__ llw,
                     const float* __restrict__ lrw,
                     const float* __restrict__ rsw)
{
    int idx = blockIdx.x * blockDim.x + threadIdx.x;
    if (idx >= 256 * 256) return;
    const int k = idx >> 8;
    const int c = idx & 255;
    const int j = c >> 1;
    float v;
    if ((c & 1) == 0)
        v = (k < 128) ? llw[(size_t)k * 128 + j] : lrw[(size_t)(k - 128) * 128 + j];
    else
        v = (k < 128) ? 0.f : rsw[(size_t)(k - 128) * 128 + j];
    g_Bc[idx] = v;
}

// ---------------- K2: edge scatter (one warp per edge) ----------------------
__global__ void k_scatter(const void* __restrict__ ei, int E) {
    const int w    = (blockIdx.x * blockDim.x + threadIdx.x) >> 5;
    const int lane = threadIdx.x & 31;
    if (w >= E) return;
    const long long src = load_idx(ei, w);
    const long long dst = load_idx(ei, E + w);
    const float4 v = *reinterpret_cast<const float4*>(g_xf + (size_t)src * 128 + lane * 4);
    float* o = g_msg + (size_t)dst * 128 + lane * 4;
    asm volatile("red.global.add.v4.f32 [%0], {%1,%2,%3,%4};"
                 :: "l"(o), "f"(v.x), "f"(v.y), "f"(v.z), "f"(v.w) : "memory");
    if (lane == 0) atomicAdd(g_cnt + dst, 1.0f);
}

// ---------------- K3: fused GEMM + epilogue ---------------------------------
// A = [agg | xf]  (K=256),  B = g_Bc (interleaved).  64x256 tile, 256 threads.
// Each thread's 8 cols are 4 (u,v) pairs -> thread-local relu+residual,
// head dot reduced across the warp (warp == one row-group x all 32 col-groups).
__global__ __launch_bounds__(256) void k_fused(
    const float* __restrict__ llb, const float* __restrict__ rsb,
    const float* __restrict__ shw, const float* __restrict__ shb,
    const float* __restrict__ alpha, const float* __restrict__ rr,
    float* __restrict__ out, int n)
{
    __shared__ float As[16][68];    // padded
    __shared__ float Bs[16][256];

    const int tid  = threadIdx.x;
    const int row0 = blockIdx.x * 64;
    const int ty   = tid >> 5;      // 8 row groups (== warp id)
    const int tx   = tid & 31;      // 32 col groups (== lane)

    float acc[8][8];
#pragma unroll
    for (int i = 0; i < 8; i++)
#pragma unroll
        for (int j = 0; j < 8; j++) acc[i][j] = 0.f;

    const int arl = tid >> 2;            // 64 rows
    const int aq  = (tid & 3) * 4;       // 0,4,8,12
    const int ar  = row0 + arl;
    float invc = 1.f;
    if (ar < n) invc = 1.f / fmaxf(g_cnt[ar], 1.f);

    for (int k0 = 0; k0 < 256; k0 += 16) {
        // ---- A fragment (agg for k<128, xf for k>=128; chunk is uniform)
        float4 va = make_float4(0.f, 0.f, 0.f, 0.f);
        if (ar < n) {
            const int k = k0 + aq;
            if (k < 128) {
                va = *reinterpret_cast<const float4*>(g_msg + (size_t)ar * 128 + k);
                va.x *= invc; va.y *= invc; va.z *= invc; va.w *= invc;
            } else {
                va = *reinterpret_cast<const float4*>(g_xf + (size_t)ar * 128 + (k - 128));
            }
        }
        // ---- B fragment: 16x256 = 1024 float4, 4 per thread
        float4 vb[4];
#pragma unroll
        for (int t = 0; t < 4; t++) {
            const int idx = tid + t * 256;
            vb[t] = *reinterpret_cast<const float4*>(
                g_Bc + (size_t)(k0 + (idx >> 6)) * 256 + (idx & 63) * 4);
        }

        __syncthreads();
        As[aq + 0][arl] = va.x;
        As[aq + 1][arl] = va.y;
        As[aq + 2][arl] = va.z;
        As[aq + 3][arl] = va.w;
#pragma unroll
        for (int t = 0; t < 4; t++) {
            const int idx = tid + t * 256;
            *reinterpret_cast<float4*>(&Bs[idx >> 6][(idx & 63) * 4]) = vb[t];
        }
        __syncthreads();

#pragma unroll
        for (int kk = 0; kk < 16; kk++) {
            float a[8], b[8];
            *reinterpret_cast<float4*>(a)     = *reinterpret_cast<const float4*>(&As[kk][ty * 8]);
            *reinterpret_cast<float4*>(a + 4) = *reinterpret_cast<const float4*>(&As[kk][ty * 8 + 4]);
            *reinterpret_cast<float4*>(b)     = *reinterpret_cast<const float4*>(&Bs[kk][tx * 8]);
            *reinterpret_cast<float4*>(b + 4) = *reinterpret_cast<const float4*>(&Bs[kk][tx * 8 + 4]);
#pragma unroll
            for (int i = 0; i < 8; i++)
#pragma unroll
                for (int j = 0; j < 8; j++)
                    acc[i][j] += a[i] * b[j];
        }
    }

    // ---- epilogue: cols tx*8+{2jj,2jj+1} are (u,v) pairs for j = tx*4+jj
    float lb[4], rb[4], sw[4];
#pragma unroll
    for (int jj = 0; jj < 4; jj++) {
        const int j = tx * 4 + jj;
        lb[jj] = llb[j];
        rb[jj] = rsb[j];
        sw[jj] = shw[j];
    }
    const float av   = alpha[0];
    const float sig  = 1.f / (1.f + expf(-av));
    const float shbv = shb[0];

#pragma unroll
    for (int i = 0; i < 8; i++) {
        float pd = 0.f;
#pragma unroll
        for (int jj = 0; jj < 4; jj++) {
            const float u = acc[i][2 * jj]     + lb[jj];
            const float v = acc[i][2 * jj + 1] + rb[jj];
            const float h = fmaxf(u, 0.f) + v;
            pd += h * sw[jj];
        }
#pragma unroll
        for (int off = 16; off > 0; off >>= 1)
            pd += __shfl_xor_sync(0xffffffffu, pd, off);
        if (tx == 0) {
            const int r = row0 + ty * 8 + i;
            if (r < n) {
                const float gnn = pd + shbv;
                out[r] = sig * rr[r] + (1.f - sig) * gnn;
            }
        }
    }
}

// ---------------- launch -----------------------------------------------------
extern "C" void kernel_launch(void* const* d_in, const int* in_sizes, int n_in,
                              void* d_out, int out_size) {
    const float* x     = (const float*)d_in[0];
    const void*  pos   = d_in[1];
    const void*  len   = d_in[2];
    const void*  ei    = d_in[3];
    const float* rr    = (const float*)d_in[4];
    const float* fpw   = (const float*)d_in[5];
    const float* fpb   = (const float*)d_in[6];
    const float* llw   = (const float*)d_in[7];
    const float* llb   = (const float*)d_in[8];
    const float* lrw   = (const float*)d_in[9];
    const float* rsw   = (const float*)d_in[10];
    const float* rsb   = (const float*)d_in[11];
    const float* shw   = (const float*)d_in[12];
    const float* shb   = (const float*)d_in[13];
    const float* alpha = (const float*)d_in[14];
    float* out = (float*)d_out;

    const int n = in_sizes[0] / DIM;
    const int E = in_sizes[3] / 2;

    k_detect<<<1, 32>>>(ei, n);
    k_zero<<<512, 256>>>(n);
    k_featproj<<<(n + 127) / 128, 256>>>(x, pos, len, fpw, fpb, n);
    k_bc<<<(256 * 256 + 255) / 256, 256>>>(llw, lrw, rsw);
    k_scatter<<<(E * 32 + 255) / 256, 256>>>(ei, E);
    k_fused<<<(n + 63) / 64, 256>>>(llb, rsb, shw, shb, alpha, rr, out, n);
}

// round 9
// speedup vs baseline: 1.0964x; 1.0964x over previous
#include <cuda_runtime.h>
#include <mma.h>
#include <cstdint>
#include <cstddef>

using namespace nvcuda;

#define NMAX 100352
#define DIM 128

// ---------------- scratch (static device globals; no allocations) ----------
__device__ float g_xf[(size_t)NMAX * DIM];     // projected features   [N,128]
__device__ float g_msg[(size_t)NMAX * DIM];    // segment sums         [N,128]
__device__ float g_cnt[NMAX];                  // in-degree (float)
__device__ float g_Bc[256 * 256];              // combined interleaved B (tf32)
__device__ float g_pd[2 * NMAX];               // per-half head-dot partials
__device__ int   g_idx64;                      // 1 if index tensors are int64

__device__ __forceinline__ float to_tf32(float x) {
    float r;
    asm("cvt.rna.tf32.f32 %0, %1;" : "=f"(r) : "f"(x));
    return r;
}

// ---------------- dtype-robust index load ----------------------------------
__device__ __forceinline__ long long load_idx(const void* p, int i) {
    if (g_idx64) return reinterpret_cast<const long long*>(p)[i];
    return (long long)reinterpret_cast<const int*>(p)[i];
}

__global__ void k_detect(const void* ei, int n) {
    if (blockIdx.x == 0 && threadIdx.x == 0) {
        const long long* p = reinterpret_cast<const long long*>(ei);
        int ok = 1;
        for (int i = 0; i < 16; i++) {
            long long v = p[i];
            if (v < 0 || v >= (long long)n) ok = 0;
        }
        g_idx64 = ok;
    }
}

// ---------------- K0: zero scratch ------------------------------------------
__global__ void k_zero(int n) {
    const float4 z = make_float4(0.f, 0.f, 0.f, 0.f);
    int total4 = n * (DIM / 4);
    for (int i = blockIdx.x * blockDim.x + threadIdx.x; i < total4;
         i += gridDim.x * blockDim.x)
        reinterpret_cast<float4*>(g_msg)[i] = z;
    for (int i = blockIdx.x * blockDim.x + threadIdx.x; i < n;
         i += gridDim.x * blockDim.x)
        g_cnt[i] = 0.f;
}

// ---------------- K_bc: combined, column-interleaved B (256x256, tf32) ------
// col 2j   : k<128 -> lin_l_w[k][j]      ; k>=128 -> lin_r_w[k-128][j]
// col 2j+1 : k<128 -> 0                  ; k>=128 -> res_w[k-128][j]
__global__ void k_bc(const float* __restrict__ llw,
                     const float* __restrict__ lrw,
                     const float* __restrict__ rsw)
{
    int idx = blockIdx.x * blockDim.x + threadIdx.x;
    if (idx >= 256 * 256) return;
    const int k = idx >> 8;
    const int c = idx & 255;
    const int j = c >> 1;
    float v;
    if ((c & 1) == 0)
        v = (k < 128) ? llw[(size_t)k * 128 + j] : lrw[(size_t)(k - 128) * 128 + j];
    else
        v = (k < 128) ? 0.f : rsw[(size_t)(k - 128) * 128 + j];
    g_Bc[idx] = to_tf32(v);
}

// ---------------- K2: edge scatter (one warp per edge) ----------------------
__global__ void k_scatter(const void* __restrict__ ei, int E) {
    const int w    = (blockIdx.x * blockDim.x + threadIdx.x) >> 5;
    const int lane = threadIdx.x & 31;
    if (w >= E) return;
    const long long src = load_idx(ei, w);
    const long long dst = load_idx(ei, E + w);
    const float4 v = *reinterpret_cast<const float4*>(g_xf + (size_t)src * 128 + lane * 4);
    float* o = g_msg + (size_t)dst * 128 + lane * 4;
    asm volatile("red.global.add.v4.f32 [%0], {%1,%2,%3,%4};"
                 :: "l"(o), "f"(v.x), "f"(v.y), "f"(v.z), "f"(v.w) : "memory");
    if (lane == 0) atomicAdd(g_cnt + dst, 1.0f);
}

// ================= WMMA tiling constants ====================================
// CTA tile 128(M) x 128(N), K-chunks of 32. SMEM: A[128][40], B[32][136], x2.
#define A_STRIDE 40
#define B_STRIDE 136
#define OFF_INVC 0
#define OFF_A0   512
#define OFF_B0   (512 + 128 * A_STRIDE * 4)                 // 512 + 20480
#define OFF_A1   (OFF_B0 + 32 * B_STRIDE * 4)               // + 17408
#define OFF_B1   (OFF_A1 + 128 * A_STRIDE * 4)
#define SM_TOTAL (OFF_B1 + 32 * B_STRIDE * 4)               // 76288
#define C_STRIDE 136

typedef wmma::fragment<wmma::matrix_a, 16, 16, 8, wmma::precision::tf32,
                       wmma::row_major> FragA;
typedef wmma::fragment<wmma::matrix_b, 16, 16, 8, wmma::precision::tf32,
                       wmma::row_major> FragB;
typedef wmma::fragment<wmma::accumulator, 16, 16, 8, float> FragC;

// ---------------- K1: xf = [x | pos/50 | len/500] @ fp_w + fp_b (WMMA) ------
// K = 130, padded to 160 -> 5 chunks of 32.
__global__ __launch_bounds__(256) void k_featproj(
    const float* __restrict__ x, const void* __restrict__ pos,
    const void* __restrict__ len, const float* __restrict__ fpw,
    const float* __restrict__ fpb, int n)
{
    extern __shared__ char smem[];
    const int tid  = threadIdx.x;
    const int wid  = tid >> 5;
    const int row0 = blockIdx.x * 128;
    const int wm   = wid & 3;          // M block of 32
    const int wn   = wid >> 2;         // N block of 64

    FragC acc[2][4];
#pragma unroll
    for (int i = 0; i < 2; i++)
#pragma unroll
        for (int j = 0; j < 4; j++) wmma::fill_fragment(acc[i][j], 0.f);

    const int NC = 5;
    float4 pa[4], pb[4];

    // ---- prefetch helpers (inlined per chunk) ----
    auto prefA = [&](int c) {
#pragma unroll
        for (int t = 0; t < 4; t++) {
            const int idx = tid + 256 * t;
            const int row = idx >> 3, f4 = idx & 7;
            const int r = row0 + row;
            const int gk0 = c * 32 + f4 * 4;
            float4 v = make_float4(0.f, 0.f, 0.f, 0.f);
            if (r < n) {
                if (gk0 + 3 < 128) {
                    v = *reinterpret_cast<const float4*>(x + (size_t)r * 128 + gk0);
                } else if (gk0 == 128) {
                    v.x = (float)load_idx(pos, r) * (1.0f / 50.0f);
                    v.y = (float)load_idx(len, r) * (1.0f / 500.0f);
                }
            }
            pa[t] = v;
        }
    };
    auto prefB = [&](int c) {
#pragma unroll
        for (int t = 0; t < 4; t++) {
            const int idx = tid + 256 * t;
            const int kr = idx >> 5, n4 = idx & 31;
            const int gk = c * 32 + kr;
            float4 v = make_float4(0.f, 0.f, 0.f, 0.f);
            if (gk < 130)
                v = *reinterpret_cast<const float4*>(fpw + (size_t)gk * 128 + n4 * 4);
            pb[t] = v;
        }
    };
    auto stageAB = [&](uint32_t aoff, uint32_t boff) {
#pragma unroll
        for (int t = 0; t < 4; t++) {
            const int idx = tid + 256 * t;
            const int row = idx >> 3, f4 = idx & 7;
            float4 v = pa[t];
            v.x = to_tf32(v.x); v.y = to_tf32(v.y);
            v.z = to_tf32(v.z); v.w = to_tf32(v.w);
            *reinterpret_cast<float4*>(smem + aoff + (row * A_STRIDE + f4 * 4) * 4) = v;
        }
#pragma unroll
        for (int t = 0; t < 4; t++) {
            const int idx = tid + 256 * t;
            const int kr = idx >> 5, n4 = idx & 31;
            float4 v = pb[t];
            v.x = to_tf32(v.x); v.y = to_tf32(v.y);
            v.z = to_tf32(v.z); v.w = to_tf32(v.w);
            *reinterpret_cast<float4*>(smem + boff + (kr * B_STRIDE + n4 * 4) * 4) = v;
        }
    };

    prefA(0); prefB(0);
    stageAB(OFF_A0, OFF_B0);
    __syncthreads();

    for (int c = 0; c < NC; c++) {
        if (c + 1 < NC) { prefA(c + 1); prefB(c + 1); }
        const uint32_t aoff = (c & 1) ? OFF_A1 : OFF_A0;
        const uint32_t boff = (c & 1) ? OFF_B1 : OFF_B0;
        const float* As = reinterpret_cast<const float*>(smem + aoff);
        const float* Bs = reinterpret_cast<const float*>(smem + boff);
#pragma unroll
        for (int ks = 0; ks < 4; ks++) {
            const int kk = ks * 8;
            FragA af[2];
            FragB bf[4];
            wmma::load_matrix_sync(af[0], As + (wm * 32 + 0)  * A_STRIDE + kk, A_STRIDE);
            wmma::load_matrix_sync(af[1], As + (wm * 32 + 16) * A_STRIDE + kk, A_STRIDE);
#pragma unroll
            for (int j = 0; j < 4; j++)
                wmma::load_matrix_sync(bf[j], Bs + kk * B_STRIDE + wn * 64 + j * 16,
                                       B_STRIDE);
#pragma unroll
            for (int i = 0; i < 2; i++)
#pragma unroll
                for (int j = 0; j < 4; j++)
                    wmma::mma_sync(acc[i][j], af[i], bf[j], acc[i][j]);
        }
        __syncthreads();
        if (c + 1 < NC) {
            stageAB((c & 1) ? OFF_A0 : OFF_A1, (c & 1) ? OFF_B0 : OFF_B1);
            __syncthreads();
        }
    }

    // ---- epilogue: store C to smem, add bias, write g_xf
    float* Cs = reinterpret_cast<float*>(smem + OFF_A0);
#pragma unroll
    for (int i = 0; i < 2; i++)
#pragma unroll
        for (int j = 0; j < 4; j++)
            wmma::store_matrix_sync(Cs + (wm * 32 + i * 16) * C_STRIDE + wn * 64 + j * 16,
                                    acc[i][j], C_STRIDE, wmma::mem_row_major);
    __syncthreads();

    {
        const int row = tid >> 1, seg = tid & 1;
        const int r = row0 + row;
        if (r < n) {
#pragma unroll
            for (int f4 = 0; f4 < 16; f4++) {
                const int col = seg * 64 + f4 * 4;
                float4 b = *reinterpret_cast<const float4*>(fpb + col);
                float4 o;
                o.x = Cs[row * C_STRIDE + col + 0] + b.x;
                o.y = Cs[row * C_STRIDE + col + 1] + b.y;
                o.z = Cs[row * C_STRIDE + col + 2] + b.z;
                o.w = Cs[row * C_STRIDE + col + 3] + b.w;
                *reinterpret_cast<float4*>(g_xf + (size_t)r * 128 + col) = o;
            }
        }
    }
}

// ---------------- K3: fused GEMM (WMMA) + epilogue partials ------------------
// A = [agg | xf] (K=256 -> 8 chunks), B = g_Bc slice cols [half*128, +128).
__global__ __launch_bounds__(256) void k_fused(
    const float* __restrict__ llb, const float* __restrict__ rsb,
    const float* __restrict__ shw, int n)
{
    extern __shared__ char smem[];
    const int tid   = threadIdx.x;
    const int wid   = tid >> 5;
    const int row0  = blockIdx.x * 128;
    const int half  = blockIdx.y;
    const int nbase = half * 128;
    const int wm    = wid & 3;
    const int wn    = wid >> 2;

    float* s_invc = reinterpret_cast<float*>(smem + OFF_INVC);
    if (tid < 128) {
        const int r = row0 + tid;
        s_invc[tid] = (r < n) ? (1.f / fmaxf(g_cnt[r], 1.f)) : 0.f;
    }
    __syncthreads();

    FragC acc[2][4];
#pragma unroll
    for (int i = 0; i < 2; i++)
#pragma unroll
        for (int j = 0; j < 4; j++) wmma::fill_fragment(acc[i][j], 0.f);

    const int NC = 8;
    float4 pa[4], pb[4];

    auto prefA = [&](int c) {
#pragma unroll
        for (int t = 0; t < 4; t++) {
            const int idx = tid + 256 * t;
            const int row = idx >> 3, f4 = idx & 7;
            const int r = row0 + row;
            float4 v = make_float4(0.f, 0.f, 0.f, 0.f);
            if (r < n) {
                if (c < 4)
                    v = *reinterpret_cast<const float4*>(
                        g_msg + (size_t)r * 128 + c * 32 + f4 * 4);
                else
                    v = *reinterpret_cast<const float4*>(
                        g_xf + (size_t)r * 128 + (c - 4) * 32 + f4 * 4);
            }
            pa[t] = v;
        }
    };
    auto prefB = [&](int c) {
#pragma unroll
        for (int t = 0; t < 4; t++) {
            const int idx = tid + 256 * t;
            const int kr = idx >> 5, n4 = idx & 31;
            pb[t] = *reinterpret_cast<const float4*>(
                g_Bc + (size_t)(c * 32 + kr) * 256 + nbase + n4 * 4);
        }
    };
    auto stageAB = [&](int c, uint32_t aoff, uint32_t boff) {
#pragma unroll
        for (int t = 0; t < 4; t++) {
            const int idx = tid + 256 * t;
            const int row = idx >> 3, f4 = idx & 7;
            float4 v = pa[t];
            if (c < 4) {
                const float s = s_invc[row];
                v.x *= s; v.y *= s; v.z *= s; v.w *= s;
            }
            v.x = to_tf32(v.x); v.y = to_tf32(v.y);
            v.z = to_tf32(v.z); v.w = to_tf32(v.w);
            *reinterpret_cast<float4*>(smem + aoff + (row * A_STRIDE + f4 * 4) * 4) = v;
        }
#pragma unroll
        for (int t = 0; t < 4; t++) {
            const int idx = tid + 256 * t;
            const int kr = idx >> 5, n4 = idx & 31;
            *reinterpret_cast<float4*>(smem + boff + (kr * B_STRIDE + n4 * 4) * 4) = pb[t];
        }
    };

    prefA(0); prefB(0);
    stageAB(0, OFF_A0, OFF_B0);
    __syncthreads();

    for (int c = 0; c < NC; c++) {
        if (c + 1 < NC) { prefA(c + 1); prefB(c + 1); }
        const uint32_t aoff = (c & 1) ? OFF_A1 : OFF_A0;
        const uint32_t boff = (c & 1) ? OFF_B1 : OFF_B0;
        const float* As = reinterpret_cast<const float*>(smem + aoff);
        const float* Bs = reinterpret_cast<const float*>(smem + boff);
#pragma unroll
        for (int ks = 0; ks < 4; ks++) {
            const int kk = ks * 8;
            FragA af[2];
            FragB bf[4];
            wmma::load_matrix_sync(af[0], As + (wm * 32 + 0)  * A_STRIDE + kk, A_STRIDE);
            wmma::load_matrix_sync(af[1], As + (wm * 32 + 16) * A_STRIDE + kk, A_STRIDE);
#pragma unroll
            for (int j = 0; j < 4; j++)
                wmma::load_matrix_sync(bf[j], Bs + kk * B_STRIDE + wn * 64 + j * 16,
                                       B_STRIDE);
#pragma unroll
            for (int i = 0; i < 2; i++)
#pragma unroll
                for (int j = 0; j < 4; j++)
                    wmma::mma_sync(acc[i][j], af[i], bf[j], acc[i][j]);
        }
        __syncthreads();
        if (c + 1 < NC) {
            stageAB(c + 1, (c & 1) ? OFF_A0 : OFF_A1, (c & 1) ? OFF_B0 : OFF_B1);
            __syncthreads();
        }
    }

    // ---- epilogue: relu/residual/head-dot partial for this N-half
    float* Cs = reinterpret_cast<float*>(smem + OFF_A0);
#pragma unroll
    for (int i = 0; i < 2; i++)
#pragma unroll
        for (int j = 0; j < 4; j++)
            wmma::store_matrix_sync(Cs + (wm * 32 + i * 16) * C_STRIDE + wn * 64 + j * 16,
                                    acc[i][j], C_STRIDE, wmma::mem_row_major);
    __syncthreads();

    {
        const int row = tid >> 1, seg = tid & 1;
        const float* crow = Cs + row * C_STRIDE + seg * 64;
        float pd = 0.f;
#pragma unroll
        for (int jj = 0; jj < 32; jj++) {
            const int j = half * 64 + seg * 32 + jj;
            const float u = crow[2 * jj]     + llb[j];
            const float v = crow[2 * jj + 1] + rsb[j];
            pd += (fmaxf(u, 0.f) + v) * shw[j];
        }
        pd += __shfl_xor_sync(0xffffffffu, pd, 1);
        const int r = row0 + row;
        if (seg == 0 && r < n)
            g_pd[(size_t)half * NMAX + r] = pd;
    }
}

// ---------------- K4: combine halves + blend --------------------------------
__global__ void k_combine(const float* __restrict__ rr,
                          const float* __restrict__ shb,
                          const float* __restrict__ alpha,
                          float* __restrict__ out, int n)
{
    const int r = blockIdx.x * blockDim.x + threadIdx.x;
    if (r >= n) return;
    const float gnn = g_pd[r] + g_pd[NMAX + r] + shb[0];
    const float a   = alpha[0];
    const float sig = 1.f / (1.f + expf(-a));
    out[r] = sig * rr[r] + (1.f - sig) * gnn;
}

// ---------------- launch -----------------------------------------------------
extern "C" void kernel_launch(void* const* d_in, const int* in_sizes, int n_in,
                              void* d_out, int out_size) {
    const float* x     = (const float*)d_in[0];
    const void*  pos   = d_in[1];
    const void*  len   = d_in[2];
    const void*  ei    = d_in[3];
    const float* rr    = (const float*)d_in[4];
    const float* fpw   = (const float*)d_in[5];
    const float* fpb   = (const float*)d_in[6];
    const float* llw   = (const float*)d_in[7];
    const float* llb   = (const float*)d_in[8];
    const float* lrw   = (const float*)d_in[9];
    const float* rsw   = (const float*)d_in[10];
    const float* rsb   = (const float*)d_in[11];
    const float* shw   = (const float*)d_in[12];
    const float* shb   = (const float*)d_in[13];
    const float* alpha = (const float*)d_in[14];
    float* out = (float*)d_out;

    const int n = in_sizes[0] / DIM;
    const int E = in_sizes[3] / 2;

    cudaFuncSetAttribute(k_featproj, cudaFuncAttributeMaxDynamicSharedMemorySize,
                         SM_TOTAL);
    cudaFuncSetAttribute(k_fused, cudaFuncAttributeMaxDynamicSharedMemorySize,
                         SM_TOTAL);

    k_detect<<<1, 32>>>(ei, n);
    k_zero<<<512, 256>>>(n);
    k_featproj<<<(n + 127) / 128, 256, SM_TOTAL>>>(x, pos, len, fpw, fpb, n);
    k_bc<<<(256 * 256 + 255) / 256, 256>>>(llw, lrw, rsw);
    k_scatter<<<(E * 32 + 255) / 256, 256>>>(ei, E);
    k_fused<<<dim3((n + 127) / 128, 2), 256, SM_TOTAL>>>(llb, rsb, shw, n);
    k_combine<<<(n + 255) / 256, 256>>>(rr, shb, alpha, out, n);
}